// round 16
// baseline (speedup 1.0000x reference)
#include <cuda_runtime.h>
#include <cuda_fp16.h>
#include <math.h>

typedef unsigned long long ull;

// ---------------- static scratch (no allocs) --------------------------------
#define NSMAX 1000000
#define NDMAX 100000
#define BCAP  128                          // per-dst bucket (2 shards x 64)
#define SCAP  64                           // per-shard capacity

__device__ int    g_cursor[NDMAX * 2];     // 2 shards per dst
__device__ int    g_permb[NDMAX * BCAP];   // [dst][shard*64 + slot]
__device__ __half g_hsrc[NSMAX * 32];      // [Ns][d][mean,max] interleaved half2
__device__ __half g_tmp[NDMAX * 128];      // [Nd][k*64 + stat*16 + d], fp16

#define LOG_AVG 3.4965075614664802f        // log(33.0)

// ---------------- f32x2 helpers ---------------------------------------------
__device__ __forceinline__ void fma2(ull& acc, ull a, ull b) {
    asm("fma.rn.f32x2 %0, %1, %2, %0;" : "+l"(acc) : "l"(a), "l"(b));
}
__device__ __forceinline__ float hsum2(ull v) {
    float lo, hi;
    asm("mov.b64 {%0,%1}, %2;" : "=f"(lo), "=f"(hi) : "l"(v));
    return lo + hi;
}

// ---------------- k_zero: reset bucket cursors -------------------------------
__global__ __launch_bounds__(512) void k_zero(int Nd) {
    int i = blockIdx.x * blockDim.x + threadIdx.x;
    int tot = Nd * 2;
    int n4 = tot >> 2;
    if (i < n4) ((int4*)g_cursor)[i] = make_int4(0, 0, 0, 0);
    if (i < (tot & 3)) g_cursor[n4 * 4 + i] = 0;
}

// ---------------- k_hsrc: node embedding build (forked branch) ---------------
__global__ __launch_bounds__(256) void k_hsrc(
    const int* __restrict__ Cat_src, const float* __restrict__ w, int Ns)
{
    int gtid = blockIdx.x * blockDim.x + threadIdx.x;
    int gstride = gridDim.x * blockDim.x;
    int lane = threadIdx.x & 31;
    int half = lane >> 4;
    int j = lane & 15;
    __half2* H = (__half2*)g_hsrc;
    int gw = gtid >> 5;
    int wstride = gstride >> 5;
    int nquads = (Ns + 3) >> 2;
    for (int q = gw; q < nquads; q += wstride) {
        int nA = q * 4 + half;
        int nB = nA + 2;
        if (nA < Ns) {
            int4 cA = ((const int4*)Cat_src)[nA];
            int4 cB = (nB < Ns) ? ((const int4*)Cat_src)[nB] : cA;
            float a0 = w[cA.x * 16 + j], a1 = w[cA.y * 16 + j];
            float a2 = w[cA.z * 16 + j], a3 = w[cA.w * 16 + j];
            float b0 = w[cB.x * 16 + j], b1 = w[cB.y * 16 + j];
            float b2 = w[cB.z * 16 + j], b3 = w[cB.w * 16 + j];
            float meA = (a0 + a1 + a2 + a3) * 0.25f;
            float maA = fmaxf(fmaxf(a0, a1), fmaxf(a2, a3));
            float meB = (b0 + b1 + b2 + b3) * 0.25f;
            float maB = fmaxf(fmaxf(b0, b1), fmaxf(b2, b3));
            H[nA * 16 + j] = __floats2half2_rn(meA, maA);
            if (nB < Ns) H[nB * 16 + j] = __floats2half2_rn(meB, maB);
        }
    }
}

// ---------------- k_scatter: sharded bucket scatter --------------------------
__global__ __launch_bounds__(256) void k_scatter(
    const int* __restrict__ src, const int* __restrict__ dst, int E)
{
    int e4 = E >> 2;
#pragma unroll
    for (int u = 0; u < 2; u++) {
        int i = blockIdx.x * 512 + u * 256 + threadIdx.x;
        if (i < e4) {
            int sh = i & 1;                     // shard by chunk parity
            int shoff = sh << 6;
            int4 s = __ldcs(&((const int4*)src)[i]);
            int4 d = __ldcs(&((const int4*)dst)[i]);
            int p0 = atomicAdd(&g_cursor[d.x * 2 + sh], 1);
            int p1 = atomicAdd(&g_cursor[d.y * 2 + sh], 1);
            int p2 = atomicAdd(&g_cursor[d.z * 2 + sh], 1);
            int p3 = atomicAdd(&g_cursor[d.w * 2 + sh], 1);
            if (p0 < SCAP) g_permb[(d.x << 7) + shoff + p0] = s.x;
            if (p1 < SCAP) g_permb[(d.y << 7) + shoff + p1] = s.y;
            if (p2 < SCAP) g_permb[(d.z << 7) + shoff + p2] = s.z;
            if (p3 < SCAP) g_permb[(d.w << 7) + shoff + p3] = s.w;
        }
    }
    int t = blockIdx.x * 512 + threadIdx.x;
    if (t < (E & 3)) {
        int e = e4 * 4 + t;
        int d = dst[e];
        int p = atomicAdd(&g_cursor[d * 2], 1);
        if (p < SCAP) g_permb[(d << 7) + p] = src[e];
    }
}

// ---------------- k_agg: 2 dst-nodes per warp, half2, reg-capped ------------
__global__ __launch_bounds__(256, 8) void k_agg(int Nd)
{
    int lane = threadIdx.x & 31;
    int half = lane >> 4;
    int j = lane & 15;
    int n = (((blockIdx.x * 256 + threadIdx.x) >> 5) << 1) + half;
    if (n >= Nd) return;

    int base = n << 7;
    int c0 = g_cursor[n * 2];     if (c0 > SCAP) c0 = SCAP;
    int c1 = g_cursor[n * 2 + 1]; if (c1 > SCAP) c1 = SCAP;
    const __half2* H = (const __half2*)g_hsrc;

    __half2 s  = __floats2half2_rn(0.f, 0.f);
    __half2 q  = s;
    __half2 mn = __floats2half2_rn( 65504.f,  65504.f);
    __half2 mx = __floats2half2_rn(-65504.f, -65504.f);

#pragma unroll 1
    for (int sg = 0; sg < 2; sg++) {
        int i = base + (sg << 6);
        int end = i + (sg ? c1 : c0);
        for (; i + 3 < end; i += 4) {
            int4 pp = *(const int4*)&g_permb[i];   // 16B-aligned (base & base+64)
            __half2 a = H[pp.x * 16 + j];
            __half2 b = H[pp.y * 16 + j];
            __half2 c = H[pp.z * 16 + j];
            __half2 e = H[pp.w * 16 + j];
            s = __hadd2(s, __hadd2(__hadd2(a, b), __hadd2(c, e)));
            q = __hfma2(a, a, q); q = __hfma2(b, b, q);
            q = __hfma2(c, c, q); q = __hfma2(e, e, q);
            mn = __hmin2(mn, __hmin2(__hmin2(a, b), __hmin2(c, e)));
            mx = __hmax2(mx, __hmax2(__hmax2(a, b), __hmax2(c, e)));
        }
        for (; i < end; i++) {
            __half2 a = H[g_permb[i] * 16 + j];
            s = __hadd2(s, a); q = __hfma2(a, a, q);
            mn = __hmin2(mn, a); mx = __hmax2(mx, a);
        }
    }

    float2 sf = __half22float2(s);
    float2 qf = __half22float2(q);
    float2 mnf = __half22float2(mn);
    float2 mxf = __half22float2(mx);

    int deg_i = c0 + c1;
    float deg = (float)deg_i;
    float inv = 1.f / fmaxf(deg, 1.f);
    bool has = deg > 0.f;
    float mean0 = sf.x * inv, mean1 = sf.y * inv;
    float sd0 = sqrtf(fmaxf(qf.x * inv - mean0 * mean0, 0.f) + 1e-5f);
    float sd1 = sqrtf(fmaxf(qf.y * inv - mean1 * mean1, 0.f) + 1e-5f);
    float mn0 = has ? mnf.x : 0.f, mn1 = has ? mnf.y : 0.f;
    float mx0 = has ? mxf.x : 0.f, mx1 = has ? mxf.y : 0.f;

    __half* t = g_tmp + n * 128;
    t[j]       = __float2half_rn(mean0);
    t[16 + j]  = __float2half_rn(mn0);
    t[32 + j]  = __float2half_rn(mx0);
    t[48 + j]  = __float2half_rn(sd0);
    t[64 + j]  = __float2half_rn(mean1);
    t[80 + j]  = __float2half_rn(mn1);
    t[96 + j]  = __float2half_rn(mx1);
    t[112 + j] = __float2half_rn(sd1);
}

// ---------------- k_mlp: 48-node tiles, 6 nodes/warp, 2 blocks/SM, PDL ------
#define SM2_WAGG  0        // 6176
#define SM2_W1    6176     // 6144
#define SM2_W2    12320    // 2048
#define SM2_BAGG  14368    // 32
#define SM2_B1    14400    // 64
#define SM2_B2    14464    // 32
#define SM2_W3    14496    // 32
#define SM2_WLIN  14528    // 96
#define SM2_MISC  14624    // 2
#define SM2_AMP   14628    // 48
#define SM2_ATT   14676    // 48
#define SM2_CD    14724    // 192 ints
#define SM2_TMP   14916    // 48 nodes * 136 (k pitch 68); aliased by h1 (pitch 68)
#define SM2_X     21444    // 48 nodes * 100
#define SM2_TOTAL (21444 + 48 * 100)   // 26244 floats = 104976 B

__global__ __launch_bounds__(256, 2) void k_mlp(
    const int* __restrict__ Cat_dst, const int* __restrict__ label,
    const float* __restrict__ w,
    const float* __restrict__ W_agg, const float* __restrict__ b_agg,
    const float* __restrict__ w_lin, const float* __restrict__ b_lin,
    const float* __restrict__ W1, const float* __restrict__ b1,
    const float* __restrict__ W2, const float* __restrict__ b2,
    const float* __restrict__ W3, const float* __restrict__ b3,
    float* __restrict__ out, int Nd, int write_label)
{
    extern __shared__ float sm[];
    int tid = threadIdx.x;
    int lane = tid & 31, warp = tid >> 5;
    int k = lane >> 4, d = lane & 15;
    int* cd_s = (int*)(sm + SM2_CD);

    // ---- weight staging: depends only on kernel inputs (pre-PDL-sync) ----
    for (int i = tid; i < 6144; i += 256) {
        int kk = i / 3072;
        int r = i - kk * 3072;
        int sec = r >> 10;
        int rr = r & 1023;
        int ff = rr >> 4, dd = rr & 15;
        sm[SM2_WAGG + kk * 3088 + sec * 1024 + (ff >> 1) * 32 + dd * 2 + (ff & 1)] = W_agg[i];
        int f1 = i >> 6, o1 = i & 63;
        sm[SM2_W1 + (f1 >> 1) * 128 + o1 * 2 + (f1 & 1)] = W1[i];
    }
    for (int i = tid; i < 2048; i += 256) {
        int f2_ = i >> 5, o2 = i & 31;
        sm[SM2_W2 + (f2_ >> 1) * 64 + o2 * 2 + (f2_ & 1)] = W2[i];
    }
    if (tid < 32) { sm[SM2_BAGG + tid] = b_agg[tid]; sm[SM2_B2 + tid] = b2[tid]; sm[SM2_W3 + tid] = W3[tid]; }
    if (tid >= 32 && tid < 96) sm[SM2_B1 + tid - 32] = b1[tid - 32];
    if (tid >= 96 && tid < 192) sm[SM2_WLIN + tid - 96] = w_lin[tid - 96];
    if (tid == 192) { sm[SM2_MISC + 0] = b_lin[0]; sm[SM2_MISC + 1] = b3[0]; }

    // PDL: wait for k_agg to finish before touching g_tmp / g_cursor
    cudaGridDependencySynchronize();
    __syncthreads();

    int ntiles = (Nd + 47) / 48;
    for (int t = blockIdx.x; t < ntiles; t += gridDim.x) {
        int n0 = t * 48;
        __syncthreads();

        // ---- P1: stage tmp (48 nodes x 64 half2 pairs), Cat_dst, amp/att ----
#pragma unroll
        for (int i = 0; i < 12; i++) {
            int g = tid + i * 256;           // 3072 half2 pairs
            int node = g >> 6, f2p = g & 63;
            int n = n0 + node; if (n >= Nd) n = Nd - 1;
            float2 fv = __half22float2(__ldcs(&((const __half2*)(g_tmp + n * 128))[f2p]));
            int f = f2p * 2;
            *(float2*)&sm[SM2_TMP + node * 136 + (f >> 6) * 68 + (f & 63)] = fv;
        }
        if (tid < 192) {
            int n = n0 + (tid >> 2); if (n >= Nd) n = Nd - 1;
            cd_s[tid] = Cat_dst[n * 4 + (tid & 3)];
        }
        if (tid < 48) {
            int n = n0 + tid; if (n >= Nd) n = Nd - 1;
            int c0 = g_cursor[n * 2];     if (c0 > SCAP) c0 = SCAP;
            int c1 = g_cursor[n * 2 + 1]; if (c1 > SCAP) c1 = SCAP;
            float deg = (float)(c0 + c1);
            float logd = logf(deg + 1.f);
            sm[SM2_AMP + tid] = logd * (1.f / LOG_AVG);
            sm[SM2_ATT + tid] = (logd > 0.f) ? (LOG_AVG / fmaxf(logd, 1e-5f)) : 0.f;
        }
        __syncthreads();

        // ---- P3: dst-embedding gathers into x[0..63] ----
#pragma unroll
        for (int i = 0; i < 12; i++) {
            int g = tid + i * 256;
            int node = g >> 6, j = g & 63;
            int ci = cd_s[node * 4 + (j >> 4)];
            sm[SM2_X + node * 100 + j] = w[ci * 16 + (j & 15)];
        }

        // ---- P2: PNA einsum (f32x2), 6 nodes per warp ----
        {
            int nw = warp * 6;
            const ull* W0 = (const ull*)(sm + SM2_WAGG + k * 3088) + d;
            const ulonglong2* T[6];
#pragma unroll
            for (int j = 0; j < 6; j++)
                T[j] = (const ulonglong2*)(sm + SM2_TMP + (nw + j) * 136 + k * 68);
            ull a0[6], a1[6], a2[6];
#pragma unroll
            for (int j = 0; j < 6; j++) { a0[j] = 0; a1[j] = 0; a2[j] = 0; }
#pragma unroll 2
            for (int f4 = 0; f4 < 16; f4++) {
                ull w00 = W0[(2 * f4) * 16],        w01 = W0[(2 * f4 + 1) * 16];
                ull w10 = W0[512 + (2 * f4) * 16],  w11 = W0[512 + (2 * f4 + 1) * 16];
                ull w20 = W0[1024 + (2 * f4) * 16], w21 = W0[1024 + (2 * f4 + 1) * 16];
#pragma unroll
                for (int j = 0; j < 6; j++) {
                    ulonglong2 v = T[j][f4];
                    fma2(a0[j], v.x, w00); fma2(a0[j], v.y, w01);
                    fma2(a1[j], v.x, w10); fma2(a1[j], v.y, w11);
                    fma2(a2[j], v.x, w20); fma2(a2[j], v.y, w21);
                }
            }
            float bg = sm[SM2_BAGG + lane];
#pragma unroll
            for (int j = 0; j < 6; j++) {
                int node = nw + j;
                sm[SM2_X + node * 100 + 64 + lane] =
                    bg + hsum2(a0[j]) + sm[SM2_AMP + node] * hsum2(a1[j])
                       + sm[SM2_ATT + node] * hsum2(a2[j]);
            }
        }
        __syncthreads();

        // ---- P4: h1 = relu(x @ W1 + b1), f32x2 ----
        float* h1_s = sm + SM2_TMP;
        {
            int nw = warp * 6;
            const ull* W1a = (const ull*)(sm + SM2_W1) + lane;
            const ulonglong2* X[6];
#pragma unroll
            for (int j = 0; j < 6; j++)
                X[j] = (const ulonglong2*)(sm + SM2_X + (nw + j) * 100);
            ull h0[6], h1r[6];
#pragma unroll
            for (int j = 0; j < 6; j++) { h0[j] = 0; h1r[j] = 0; }
#pragma unroll 2
            for (int f4 = 0; f4 < 24; f4++) {
                ull wa0 = W1a[(2 * f4) * 64],      wa1 = W1a[(2 * f4 + 1) * 64];
                ull wb0 = W1a[32 + (2 * f4) * 64], wb1 = W1a[32 + (2 * f4 + 1) * 64];
#pragma unroll
                for (int j = 0; j < 6; j++) {
                    ulonglong2 v = X[j][f4];
                    fma2(h0[j], v.x, wa0);  fma2(h0[j], v.y, wa1);
                    fma2(h1r[j], v.x, wb0); fma2(h1r[j], v.y, wb1);
                }
            }
            float b1a = sm[SM2_B1 + lane], b1b = sm[SM2_B1 + 32 + lane];
#pragma unroll
            for (int j = 0; j < 6; j++) {
                h1_s[(nw + j) * 68 + lane]      = fmaxf(hsum2(h0[j]) + b1a, 0.f);
                h1_s[(nw + j) * 68 + 32 + lane] = fmaxf(hsum2(h1r[j]) + b1b, 0.f);
            }
        }
        __syncwarp();

        // ---- P6: h2 = relu(h1 @ W2 + b2); deep partial ----
        float gdeep[6];
        {
            int nw = warp * 6;
            const ull* W2p = (const ull*)(sm + SM2_W2) + lane;
            const ulonglong2* Hh[6];
#pragma unroll
            for (int j = 0; j < 6; j++)
                Hh[j] = (const ulonglong2*)(h1_s + (nw + j) * 68);
            ull a[6];
#pragma unroll
            for (int j = 0; j < 6; j++) a[j] = 0;
#pragma unroll 2
            for (int f4 = 0; f4 < 16; f4++) {
                ull wv0 = W2p[(2 * f4) * 32], wv1 = W2p[(2 * f4 + 1) * 32];
#pragma unroll
                for (int j = 0; j < 6; j++) {
                    ulonglong2 v = Hh[j][f4];
                    fma2(a[j], v.x, wv0); fma2(a[j], v.y, wv1);
                }
            }
            float b2v = sm[SM2_B2 + lane];
            float w3v = sm[SM2_W3 + lane];
#pragma unroll
            for (int j = 0; j < 6; j++)
                gdeep[j] = fmaxf(hsum2(a[j]) + b2v, 0.f) * w3v;
        }

        // ---- P7: lin + fm per node, reduce, output ----
        {
            float wl0 = sm[SM2_WLIN + lane], wl1 = sm[SM2_WLIN + 32 + lane], wl2 = sm[SM2_WLIN + 64 + lane];
            float bl = sm[SM2_MISC + 0] + sm[SM2_MISC + 1];
#pragma unroll
            for (int j = 0; j < 6; j++) {
                int node = warp * 6 + j;
                const float* xs = sm + SM2_X + node * 100;
                float e0 = xs[lane], e1 = xs[32 + lane], e2 = xs[64 + lane];
                float lin_p = e0 * wl0 + e1 * wl1 + e2 * wl2;
                float tsum = e0 + e1 + e2;
                float qsum = e0 * e0 + e1 * e1 + e2 * e2;
                float s = tsum + __shfl_xor_sync(0xffffffffu, tsum, 16);
                float qs = qsum + __shfl_xor_sync(0xffffffffu, qsum, 16);
                float r = lin_p + gdeep[j] + 0.25f * (s * s - qs);
#pragma unroll
                for (int o = 16; o; o >>= 1)
                    r += __shfl_xor_sync(0xffffffffu, r, o);
                int n = n0 + node;
                if (lane == 0 && n < Nd) {
                    float z = r + bl;
                    out[n] = 1.f / (1.f + expf(-z));
                    if (write_label) out[Nd + n] = (float)label[n];
                }
            }
        }
    }
}

// ---------------- launch ----------------------------------------------------
extern "C" void kernel_launch(void* const* d_in, const int* in_sizes, int n_in,
                              void* d_out, int out_size) {
    const int*   Cat_src = (const int*)  d_in[0];
    const int*   Cat_dst = (const int*)  d_in[1];
    const int*   src_ids = (const int*)  d_in[2];
    const int*   dst_ids = (const int*)  d_in[3];
    const int*   label   = (const int*)  d_in[4];
    const float* w       = (const float*)d_in[5];
    const float* W_agg   = (const float*)d_in[6];
    const float* b_agg   = (const float*)d_in[7];
    const float* w_lin   = (const float*)d_in[8];
    const float* b_lin   = (const float*)d_in[9];
    const float* W1      = (const float*)d_in[10];
    const float* b1      = (const float*)d_in[11];
    const float* W2      = (const float*)d_in[12];
    const float* b2      = (const float*)d_in[13];
    const float* W3      = (const float*)d_in[14];
    const float* b3      = (const float*)d_in[15];

    int Ns = in_sizes[0] / 4;
    int Nd = in_sizes[1] / 4;
    int E  = in_sizes[2];
    float* out = (float*)d_out;
    int write_label = (out_size >= 2 * Nd) ? 1 : 0;

    // fork a side stream so h_src builds concurrently with zero+scatter
    cudaStream_t s2;
    cudaEvent_t ev_fork, ev_join;
    cudaStreamCreateWithFlags(&s2, cudaStreamNonBlocking);
    cudaEventCreateWithFlags(&ev_fork, cudaEventDisableTiming);
    cudaEventCreateWithFlags(&ev_join, cudaEventDisableTiming);

    cudaEventRecord(ev_fork, 0);
    cudaStreamWaitEvent(s2, ev_fork, 0);

    // branch B (side stream): node-embedding build
    k_hsrc<<<1184, 256, 0, s2>>>(Cat_src, w, Ns);
    cudaEventRecord(ev_join, s2);

    // branch A (main stream): cursor zero + sharded bucket scatter
    k_zero<<<(Nd / 2 + 511) / 512, 512>>>(Nd);
    int e4 = (E + 3) / 4;
    k_scatter<<<(e4 + 511) / 512, 256>>>(src_ids, dst_ids, E);

    // join: both branches done before aggregation
    cudaStreamWaitEvent(0, ev_join, 0);

    // segment reduction
    k_agg<<<(Nd + 15) / 16, 256>>>(Nd);

    // einsum + DeepFM, PDL: weight staging overlaps k_agg tail
    size_t smem = SM2_TOTAL * sizeof(float);
    cudaFuncSetAttribute(k_mlp, cudaFuncAttributeMaxDynamicSharedMemorySize, (int)smem);
    {
        cudaLaunchConfig_t cfg = {};
        cfg.gridDim = dim3(296, 1, 1);
        cfg.blockDim = dim3(256, 1, 1);
        cfg.dynamicSmemBytes = smem;
        cfg.stream = 0;
        cudaLaunchAttribute attrs[1];
        attrs[0].id = cudaLaunchAttributeProgrammaticStreamSerialization;
        attrs[0].val.programmaticStreamSerializationAllowed = 1;
        cfg.attrs = attrs;
        cfg.numAttrs = 1;
        cudaLaunchKernelEx(&cfg, k_mlp,
                           Cat_dst, label, w,
                           W_agg, b_agg, w_lin, b_lin,
                           W1, b1, W2, b2, W3, b3,
                           out, Nd, write_label);
    }
}

// round 17
// speedup vs baseline: 1.0414x; 1.0414x over previous
#include <cuda_runtime.h>
#include <cuda_fp16.h>
#include <math.h>

typedef unsigned long long ull;

// ---------------- static scratch (no allocs) --------------------------------
#define NSMAX 1000000
#define NDMAX 100000
#define BCAP  128                         // bucket capacity per dst (max deg ~70)

__device__ int    g_cursor[NDMAX];
__device__ int    g_permb[NDMAX * BCAP];  // bucketed edge srcs: [dst][slot]
__device__ __half g_hsrc[NSMAX * 32];     // [Ns][d][mean,max] interleaved half2 pairs
__device__ __half g_tmp[NDMAX * 128];     // [Nd][k*64 + stat*16 + d], fp16

#define LOG_AVG 3.4965075614664802f       // log(33.0)

// ---------------- f32x2 helpers ---------------------------------------------
__device__ __forceinline__ void fma2(ull& acc, ull a, ull b) {
    asm("fma.rn.f32x2 %0, %1, %2, %0;" : "+l"(acc) : "l"(a), "l"(b));
}
__device__ __forceinline__ float hsum2(ull v) {
    float lo, hi;
    asm("mov.b64 {%0,%1}, %2;" : "=f"(lo), "=f"(hi) : "l"(v));
    return lo + hi;
}

// ---------------- k_zero: reset bucket cursors -------------------------------
__global__ __launch_bounds__(512) void k_zero(int Nd) {
    int i = blockIdx.x * blockDim.x + threadIdx.x;
    int n4 = Nd >> 2;
    if (i < n4) ((int4*)g_cursor)[i] = make_int4(0, 0, 0, 0);
    if (i < (Nd & 3)) g_cursor[n4 * 4 + i] = 0;
}

// ---------------- k_hsrc: node embedding build (forked branch) ---------------
__global__ __launch_bounds__(256) void k_hsrc(
    const int* __restrict__ Cat_src, const float* __restrict__ w, int Ns)
{
    int gtid = blockIdx.x * blockDim.x + threadIdx.x;
    int gstride = gridDim.x * blockDim.x;
    int lane = threadIdx.x & 31;
    int half = lane >> 4;
    int j = lane & 15;
    __half2* H = (__half2*)g_hsrc;
    int gw = gtid >> 5;
    int wstride = gstride >> 5;
    int nquads = (Ns + 3) >> 2;
    for (int q = gw; q < nquads; q += wstride) {
        int nA = q * 4 + half;
        int nB = nA + 2;
        if (nA < Ns) {
            int4 cA = ((const int4*)Cat_src)[nA];
            int4 cB = (nB < Ns) ? ((const int4*)Cat_src)[nB] : cA;
            float a0 = w[cA.x * 16 + j], a1 = w[cA.y * 16 + j];
            float a2 = w[cA.z * 16 + j], a3 = w[cA.w * 16 + j];
            float b0 = w[cB.x * 16 + j], b1 = w[cB.y * 16 + j];
            float b2 = w[cB.z * 16 + j], b3 = w[cB.w * 16 + j];
            float meA = (a0 + a1 + a2 + a3) * 0.25f;
            float maA = fmaxf(fmaxf(a0, a1), fmaxf(a2, a3));
            float meB = (b0 + b1 + b2 + b3) * 0.25f;
            float maB = fmaxf(fmaxf(b0, b1), fmaxf(b2, b3));
            H[nA * 16 + j] = __floats2half2_rn(meA, maA);
            if (nB < Ns) H[nB * 16 + j] = __floats2half2_rn(meB, maB);
        }
    }
}

// ---------------- k_scatter: bucket scatter, 8 edges per thread --------------
__global__ __launch_bounds__(256) void k_scatter(
    const int* __restrict__ src, const int* __restrict__ dst, int E)
{
    int e4 = E >> 2;
#pragma unroll
    for (int u = 0; u < 2; u++) {
        int i = blockIdx.x * 512 + u * 256 + threadIdx.x;
        if (i < e4) {
            int4 s = __ldcs(&((const int4*)src)[i]);
            int4 d = __ldcs(&((const int4*)dst)[i]);
            int p0 = atomicAdd(&g_cursor[d.x], 1);
            int p1 = atomicAdd(&g_cursor[d.y], 1);
            int p2 = atomicAdd(&g_cursor[d.z], 1);
            int p3 = atomicAdd(&g_cursor[d.w], 1);
            if (p0 < BCAP) g_permb[(d.x << 7) + p0] = s.x;
            if (p1 < BCAP) g_permb[(d.y << 7) + p1] = s.y;
            if (p2 < BCAP) g_permb[(d.z << 7) + p2] = s.z;
            if (p3 < BCAP) g_permb[(d.w << 7) + p3] = s.w;
        }
    }
    int t = blockIdx.x * 512 + threadIdx.x;
    if (t < (E & 3)) {
        int e = e4 * 4 + t;
        int d = dst[e];
        int p = atomicAdd(&g_cursor[d], 1);
        if (p < BCAP) g_permb[(d << 7) + p] = src[e];
    }
}

// ---------------- k_agg: 2 dst-nodes per warp, half2, reg-capped ------------
__global__ __launch_bounds__(256, 8) void k_agg(int Nd)
{
    int lane = threadIdx.x & 31;
    int half = lane >> 4;
    int j = lane & 15;
    int n = (((blockIdx.x * 256 + threadIdx.x) >> 5) << 1) + half;
    if (n >= Nd) return;

    int base = n << 7;
    int deg_i = g_cursor[n]; if (deg_i > BCAP) deg_i = BCAP;
    int end = base + deg_i;
    const __half2* H = (const __half2*)g_hsrc;

    __half2 s  = __floats2half2_rn(0.f, 0.f);
    __half2 q  = s;
    __half2 mn = __floats2half2_rn( 65504.f,  65504.f);
    __half2 mx = __floats2half2_rn(-65504.f, -65504.f);

    int i = base;                          // 128-aligned: int4 loads always aligned
    for (; i + 3 < end; i += 4) {
        int4 pp = *(const int4*)&g_permb[i];
        __half2 a = H[pp.x * 16 + j];
        __half2 b = H[pp.y * 16 + j];
        __half2 c = H[pp.z * 16 + j];
        __half2 e = H[pp.w * 16 + j];
        s = __hadd2(s, __hadd2(__hadd2(a, b), __hadd2(c, e)));
        q = __hfma2(a, a, q); q = __hfma2(b, b, q);
        q = __hfma2(c, c, q); q = __hfma2(e, e, q);
        mn = __hmin2(mn, __hmin2(__hmin2(a, b), __hmin2(c, e)));
        mx = __hmax2(mx, __hmax2(__hmax2(a, b), __hmax2(c, e)));
    }
    for (; i < end; i++) {
        __half2 a = H[g_permb[i] * 16 + j];
        s = __hadd2(s, a); q = __hfma2(a, a, q);
        mn = __hmin2(mn, a); mx = __hmax2(mx, a);
    }

    float2 sf = __half22float2(s);
    float2 qf = __half22float2(q);
    float2 mnf = __half22float2(mn);
    float2 mxf = __half22float2(mx);

    float deg = (float)deg_i;
    float inv = 1.f / fmaxf(deg, 1.f);
    bool has = deg > 0.f;
    float mean0 = sf.x * inv, mean1 = sf.y * inv;
    float sd0 = sqrtf(fmaxf(qf.x * inv - mean0 * mean0, 0.f) + 1e-5f);
    float sd1 = sqrtf(fmaxf(qf.y * inv - mean1 * mean1, 0.f) + 1e-5f);
    float mn0 = has ? mnf.x : 0.f, mn1 = has ? mnf.y : 0.f;
    float mx0 = has ? mxf.x : 0.f, mx1 = has ? mxf.y : 0.f;

    __half* t = g_tmp + n * 128;
    t[j]       = __float2half_rn(mean0);
    t[16 + j]  = __float2half_rn(mn0);
    t[32 + j]  = __float2half_rn(mx0);
    t[48 + j]  = __float2half_rn(sd0);
    t[64 + j]  = __float2half_rn(mean1);
    t[80 + j]  = __float2half_rn(mn1);
    t[96 + j]  = __float2half_rn(mx1);
    t[112 + j] = __float2half_rn(sd1);
}

// ---------------- k_mlp: 48-node tiles, 6 nodes/warp, 2 blocks/SM, PDL ------
#define SM2_WAGG  0        // 6176
#define SM2_W1    6176     // 6144
#define SM2_W2    12320    // 2048
#define SM2_BAGG  14368    // 32
#define SM2_B1    14400    // 64
#define SM2_B2    14464    // 32
#define SM2_W3    14496    // 32
#define SM2_WLIN  14528    // 96
#define SM2_MISC  14624    // 2
#define SM2_AMP   14628    // 48
#define SM2_ATT   14676    // 48
#define SM2_CD    14724    // 192 ints
#define SM2_TMP   14916    // 48 nodes * 136 (k pitch 68); aliased by h1 (pitch 68)
#define SM2_X     21444    // 48 nodes * 100
#define SM2_TOTAL (21444 + 48 * 100)   // 26244 floats = 104976 B

__global__ __launch_bounds__(256, 2) void k_mlp(
    const int* __restrict__ Cat_dst, const int* __restrict__ label,
    const float* __restrict__ w,
    const float* __restrict__ W_agg, const float* __restrict__ b_agg,
    const float* __restrict__ w_lin, const float* __restrict__ b_lin,
    const float* __restrict__ W1, const float* __restrict__ b1,
    const float* __restrict__ W2, const float* __restrict__ b2,
    const float* __restrict__ W3, const float* __restrict__ b3,
    float* __restrict__ out, int Nd, int write_label)
{
    extern __shared__ float sm[];
    int tid = threadIdx.x;
    int lane = tid & 31, warp = tid >> 5;
    int k = lane >> 4, d = lane & 15;
    int* cd_s = (int*)(sm + SM2_CD);

    // ---- weight staging: depends only on kernel inputs (pre-PDL-sync) ----
    for (int i = tid; i < 6144; i += 256) {
        int kk = i / 3072;
        int r = i - kk * 3072;
        int sec = r >> 10;
        int rr = r & 1023;
        int ff = rr >> 4, dd = rr & 15;
        sm[SM2_WAGG + kk * 3088 + sec * 1024 + (ff >> 1) * 32 + dd * 2 + (ff & 1)] = W_agg[i];
        int f1 = i >> 6, o1 = i & 63;
        sm[SM2_W1 + (f1 >> 1) * 128 + o1 * 2 + (f1 & 1)] = W1[i];
    }
    for (int i = tid; i < 2048; i += 256) {
        int f2_ = i >> 5, o2 = i & 31;
        sm[SM2_W2 + (f2_ >> 1) * 64 + o2 * 2 + (f2_ & 1)] = W2[i];
    }
    if (tid < 32) { sm[SM2_BAGG + tid] = b_agg[tid]; sm[SM2_B2 + tid] = b2[tid]; sm[SM2_W3 + tid] = W3[tid]; }
    if (tid >= 32 && tid < 96) sm[SM2_B1 + tid - 32] = b1[tid - 32];
    if (tid >= 96 && tid < 192) sm[SM2_WLIN + tid - 96] = w_lin[tid - 96];
    if (tid == 192) { sm[SM2_MISC + 0] = b_lin[0]; sm[SM2_MISC + 1] = b3[0]; }

    // PDL: wait for k_agg to finish before touching g_tmp / g_cursor
    cudaGridDependencySynchronize();
    __syncthreads();

    int ntiles = (Nd + 47) / 48;
    for (int t = blockIdx.x; t < ntiles; t += gridDim.x) {
        int n0 = t * 48;
        __syncthreads();

        // ---- P1: stage tmp (48 nodes x 64 half2 pairs), Cat_dst, amp/att ----
#pragma unroll
        for (int i = 0; i < 12; i++) {
            int g = tid + i * 256;           // 3072 half2 pairs
            int node = g >> 6, f2p = g & 63;
            int n = n0 + node; if (n >= Nd) n = Nd - 1;
            float2 fv = __half22float2(__ldcs(&((const __half2*)(g_tmp + n * 128))[f2p]));
            int f = f2p * 2;
            *(float2*)&sm[SM2_TMP + node * 136 + (f >> 6) * 68 + (f & 63)] = fv;
        }
        if (tid < 192) {
            int n = n0 + (tid >> 2); if (n >= Nd) n = Nd - 1;
            cd_s[tid] = Cat_dst[n * 4 + (tid & 3)];
        }
        if (tid < 48) {
            int n = n0 + tid; if (n >= Nd) n = Nd - 1;
            int dg = g_cursor[n]; if (dg > BCAP) dg = BCAP;
            float deg = (float)dg;
            float logd = logf(deg + 1.f);
            sm[SM2_AMP + tid] = logd * (1.f / LOG_AVG);
            sm[SM2_ATT + tid] = (logd > 0.f) ? (LOG_AVG / fmaxf(logd, 1e-5f)) : 0.f;
        }
        __syncthreads();

        // ---- P3: dst-embedding gathers into x[0..63] ----
#pragma unroll
        for (int i = 0; i < 12; i++) {
            int g = tid + i * 256;
            int node = g >> 6, j = g & 63;
            int ci = cd_s[node * 4 + (j >> 4)];
            sm[SM2_X + node * 100 + j] = w[ci * 16 + (j & 15)];
        }

        // ---- P2: PNA einsum (f32x2), 6 nodes per warp ----
        {
            int nw = warp * 6;
            const ull* W0 = (const ull*)(sm + SM2_WAGG + k * 3088) + d;
            const ulonglong2* T[6];
#pragma unroll
            for (int j = 0; j < 6; j++)
                T[j] = (const ulonglong2*)(sm + SM2_TMP + (nw + j) * 136 + k * 68);
            ull a0[6], a1[6], a2[6];
#pragma unroll
            for (int j = 0; j < 6; j++) { a0[j] = 0; a1[j] = 0; a2[j] = 0; }
#pragma unroll 2
            for (int f4 = 0; f4 < 16; f4++) {
                ull w00 = W0[(2 * f4) * 16],        w01 = W0[(2 * f4 + 1) * 16];
                ull w10 = W0[512 + (2 * f4) * 16],  w11 = W0[512 + (2 * f4 + 1) * 16];
                ull w20 = W0[1024 + (2 * f4) * 16], w21 = W0[1024 + (2 * f4 + 1) * 16];
#pragma unroll
                for (int j = 0; j < 6; j++) {
                    ulonglong2 v = T[j][f4];
                    fma2(a0[j], v.x, w00); fma2(a0[j], v.y, w01);
                    fma2(a1[j], v.x, w10); fma2(a1[j], v.y, w11);
                    fma2(a2[j], v.x, w20); fma2(a2[j], v.y, w21);
                }
            }
            float bg = sm[SM2_BAGG + lane];
#pragma unroll
            for (int j = 0; j < 6; j++) {
                int node = nw + j;
                sm[SM2_X + node * 100 + 64 + lane] =
                    bg + hsum2(a0[j]) + sm[SM2_AMP + node] * hsum2(a1[j])
                       + sm[SM2_ATT + node] * hsum2(a2[j]);
            }
        }
        __syncthreads();

        // ---- P4: h1 = relu(x @ W1 + b1), f32x2 ----
        float* h1_s = sm + SM2_TMP;
        {
            int nw = warp * 6;
            const ull* W1a = (const ull*)(sm + SM2_W1) + lane;
            const ulonglong2* X[6];
#pragma unroll
            for (int j = 0; j < 6; j++)
                X[j] = (const ulonglong2*)(sm + SM2_X + (nw + j) * 100);
            ull h0[6], h1r[6];
#pragma unroll
            for (int j = 0; j < 6; j++) { h0[j] = 0; h1r[j] = 0; }
#pragma unroll 2
            for (int f4 = 0; f4 < 24; f4++) {
                ull wa0 = W1a[(2 * f4) * 64],      wa1 = W1a[(2 * f4 + 1) * 64];
                ull wb0 = W1a[32 + (2 * f4) * 64], wb1 = W1a[32 + (2 * f4 + 1) * 64];
#pragma unroll
                for (int j = 0; j < 6; j++) {
                    ulonglong2 v = X[j][f4];
                    fma2(h0[j], v.x, wa0);  fma2(h0[j], v.y, wa1);
                    fma2(h1r[j], v.x, wb0); fma2(h1r[j], v.y, wb1);
                }
            }
            float b1a = sm[SM2_B1 + lane], b1b = sm[SM2_B1 + 32 + lane];
#pragma unroll
            for (int j = 0; j < 6; j++) {
                h1_s[(nw + j) * 68 + lane]      = fmaxf(hsum2(h0[j]) + b1a, 0.f);
                h1_s[(nw + j) * 68 + 32 + lane] = fmaxf(hsum2(h1r[j]) + b1b, 0.f);
            }
        }
        __syncwarp();

        // ---- P6: h2 = relu(h1 @ W2 + b2); deep partial ----
        float gdeep[6];
        {
            int nw = warp * 6;
            const ull* W2p = (const ull*)(sm + SM2_W2) + lane;
            const ulonglong2* Hh[6];
#pragma unroll
            for (int j = 0; j < 6; j++)
                Hh[j] = (const ulonglong2*)(h1_s + (nw + j) * 68);
            ull a[6];
#pragma unroll
            for (int j = 0; j < 6; j++) a[j] = 0;
#pragma unroll 2
            for (int f4 = 0; f4 < 16; f4++) {
                ull wv0 = W2p[(2 * f4) * 32], wv1 = W2p[(2 * f4 + 1) * 32];
#pragma unroll
                for (int j = 0; j < 6; j++) {
                    ulonglong2 v = Hh[j][f4];
                    fma2(a[j], v.x, wv0); fma2(a[j], v.y, wv1);
                }
            }
            float b2v = sm[SM2_B2 + lane];
            float w3v = sm[SM2_W3 + lane];
#pragma unroll
            for (int j = 0; j < 6; j++)
                gdeep[j] = fmaxf(hsum2(a[j]) + b2v, 0.f) * w3v;
        }

        // ---- P7: lin + fm per node, reduce, output ----
        {
            float wl0 = sm[SM2_WLIN + lane], wl1 = sm[SM2_WLIN + 32 + lane], wl2 = sm[SM2_WLIN + 64 + lane];
            float bl = sm[SM2_MISC + 0] + sm[SM2_MISC + 1];
#pragma unroll
            for (int j = 0; j < 6; j++) {
                int node = warp * 6 + j;
                const float* xs = sm + SM2_X + node * 100;
                float e0 = xs[lane], e1 = xs[32 + lane], e2 = xs[64 + lane];
                float lin_p = e0 * wl0 + e1 * wl1 + e2 * wl2;
                float tsum = e0 + e1 + e2;
                float qsum = e0 * e0 + e1 * e1 + e2 * e2;
                float s = tsum + __shfl_xor_sync(0xffffffffu, tsum, 16);
                float qs = qsum + __shfl_xor_sync(0xffffffffu, qsum, 16);
                float r = lin_p + gdeep[j] + 0.25f * (s * s - qs);
#pragma unroll
                for (int o = 16; o; o >>= 1)
                    r += __shfl_xor_sync(0xffffffffu, r, o);
                int n = n0 + node;
                if (lane == 0 && n < Nd) {
                    float z = r + bl;
                    out[n] = 1.f / (1.f + expf(-z));
                    if (write_label) out[Nd + n] = (float)label[n];
                }
            }
        }
    }
}

// ---------------- launch ----------------------------------------------------
extern "C" void kernel_launch(void* const* d_in, const int* in_sizes, int n_in,
                              void* d_out, int out_size) {
    const int*   Cat_src = (const int*)  d_in[0];
    const int*   Cat_dst = (const int*)  d_in[1];
    const int*   src_ids = (const int*)  d_in[2];
    const int*   dst_ids = (const int*)  d_in[3];
    const int*   label   = (const int*)  d_in[4];
    const float* w       = (const float*)d_in[5];
    const float* W_agg   = (const float*)d_in[6];
    const float* b_agg   = (const float*)d_in[7];
    const float* w_lin   = (const float*)d_in[8];
    const float* b_lin   = (const float*)d_in[9];
    const float* W1      = (const float*)d_in[10];
    const float* b1      = (const float*)d_in[11];
    const float* W2      = (const float*)d_in[12];
    const float* b2      = (const float*)d_in[13];
    const float* W3      = (const float*)d_in[14];
    const float* b3      = (const float*)d_in[15];

    int Ns = in_sizes[0] / 4;
    int Nd = in_sizes[1] / 4;
    int E  = in_sizes[2];
    float* out = (float*)d_out;
    int write_label = (out_size >= 2 * Nd) ? 1 : 0;

    // fork a side stream so h_src builds concurrently with zero+scatter
    cudaStream_t s2;
    cudaEvent_t ev_fork, ev_join;
    cudaStreamCreateWithFlags(&s2, cudaStreamNonBlocking);
    cudaEventCreateWithFlags(&ev_fork, cudaEventDisableTiming);
    cudaEventCreateWithFlags(&ev_join, cudaEventDisableTiming);

    cudaEventRecord(ev_fork, 0);
    cudaStreamWaitEvent(s2, ev_fork, 0);

    // branch B (side stream): node-embedding build
    k_hsrc<<<1184, 256, 0, s2>>>(Cat_src, w, Ns);
    cudaEventRecord(ev_join, s2);

    // branch A (main stream): cursor zero + bucket scatter
    k_zero<<<(Nd / 4 + 511) / 512, 512>>>(Nd);
    int e4 = (E + 3) / 4;
    k_scatter<<<(e4 + 511) / 512, 256>>>(src_ids, dst_ids, E);

    // join: both branches done before aggregation
    cudaStreamWaitEvent(0, ev_join, 0);

    // segment reduction
    k_agg<<<(Nd + 15) / 16, 256>>>(Nd);

    // einsum + DeepFM, PDL: weight staging overlaps k_agg tail
    size_t smem = SM2_TOTAL * sizeof(float);
    cudaFuncSetAttribute(k_mlp, cudaFuncAttributeMaxDynamicSharedMemorySize, (int)smem);
    {
        cudaLaunchConfig_t cfg = {};
        cfg.gridDim = dim3(296, 1, 1);
        cfg.blockDim = dim3(256, 1, 1);
        cfg.dynamicSmemBytes = smem;
        cfg.stream = 0;
        cudaLaunchAttribute attrs[1];
        attrs[0].id = cudaLaunchAttributeProgrammaticStreamSerialization;
        attrs[0].val.programmaticStreamSerializationAllowed = 1;
        cfg.attrs = attrs;
        cfg.numAttrs = 1;
        cudaLaunchKernelEx(&cfg, k_mlp,
                           Cat_dst, label, w,
                           W_agg, b_agg, w_lin, b_lin,
                           W1, b1, W2, b2, W3, b3,
                           out, Nd, write_label);
    }
}